// round 10
// baseline (speedup 1.0000x reference)
#include <cuda_runtime.h>
#include <cuda_bf16.h>
#include <math.h>
#include <stdint.h>

// ---------------------------------------------------------------------------
// Encoder layer: B=1, S=4096, D=1024, H=16, dk=64, F=4096, fp32 in/out.
// GEMMs: tf32 mma.sync, BM=128 BN=256 (1 CTA/SM, 255-reg budget), ldmatrix
// a-frags, explicit fragment double-buffering. Attention: bf16 m16n8k16
// (unchanged from R9).
// ---------------------------------------------------------------------------

#define S_LEN 4096
#define D_MODEL 1024
#define D_FF 4096
#define NUM_HEADS 16
#define DK 64
#define QKV_N 3072

__device__ float g_h1[S_LEN * D_MODEL];
__device__ __nv_bfloat16 g_Qb[S_LEN * D_MODEL];
__device__ __nv_bfloat16 g_Kb[S_LEN * D_MODEL];
__device__ float g_V [S_LEN * D_MODEL];
__device__ __nv_bfloat16 g_Vt[D_MODEL * S_LEN];   // [dim][key]
__device__ float g_ctx[S_LEN * D_MODEL];
__device__ float g_x1[S_LEN * D_MODEL];
__device__ float g_h2[S_LEN * D_MODEL];
__device__ float g_f1[S_LEN * D_FF];
__device__ float g_W3[D_MODEL * QKV_N];
__device__ float g_b3[QKV_N];

// ---------------------------------------------------------------------------
__device__ __forceinline__ void mma_tf32(float (&d)[4],
    const uint32_t (&a)[4], uint32_t b0, uint32_t b1)
{
    asm volatile(
        "mma.sync.aligned.m16n8k8.row.col.f32.tf32.tf32.f32 "
        "{%0,%1,%2,%3}, {%4,%5,%6,%7}, {%8,%9}, {%0,%1,%2,%3};\n"
        : "+f"(d[0]), "+f"(d[1]), "+f"(d[2]), "+f"(d[3])
        : "r"(a[0]), "r"(a[1]), "r"(a[2]), "r"(a[3]), "r"(b0), "r"(b1));
}
__device__ __forceinline__ void mma_bf16(float (&d)[4],
    const uint32_t (&a)[4], uint32_t b0, uint32_t b1)
{
    asm volatile(
        "mma.sync.aligned.m16n8k16.row.col.f32.bf16.bf16.f32 "
        "{%0,%1,%2,%3}, {%4,%5,%6,%7}, {%8,%9}, {%0,%1,%2,%3};\n"
        : "+f"(d[0]), "+f"(d[1]), "+f"(d[2]), "+f"(d[3])
        : "r"(a[0]), "r"(a[1]), "r"(a[2]), "r"(a[3]), "r"(b0), "r"(b1));
}
__device__ __forceinline__ void ldsm_x4(uint32_t (&d)[4], uint32_t saddr) {
    asm volatile("ldmatrix.sync.aligned.m8n8.x4.shared.b16 {%0,%1,%2,%3}, [%4];"
        : "=r"(d[0]), "=r"(d[1]), "=r"(d[2]), "=r"(d[3]) : "r"(saddr));
}
__device__ __forceinline__ void ldsm_x2(uint32_t& d0, uint32_t& d1, uint32_t saddr) {
    asm volatile("ldmatrix.sync.aligned.m8n8.x2.shared.b16 {%0,%1}, [%2];"
        : "=r"(d0), "=r"(d1) : "r"(saddr));
}
__device__ __forceinline__ uint32_t f2u(float x) { return __float_as_uint(x); }
__device__ __forceinline__ uint32_t smem_u32(const void* p) {
    return (uint32_t)__cvta_generic_to_shared(p);
}
__device__ __forceinline__ uint32_t pack_bf16(float lo, float hi) {
    __nv_bfloat162 v = __floats2bfloat162_rn(lo, hi);
    return *(uint32_t*)&v;
}
#define CP_ASYNC16(dst, src) \
    asm volatile("cp.async.cg.shared.global [%0], [%1], 16;\n" :: "r"(dst), "l"(src))
#define CP_COMMIT() asm volatile("cp.async.commit_group;\n")
#define CP_WAIT(n)  asm volatile("cp.async.wait_group %0;\n" :: "n"(n))

__device__ __forceinline__ float ex2(float x) {
    float y;
    asm("ex2.approx.f32 %0, %1;" : "=f"(y) : "f"(x));
    return y;
}

// ---------------------------------------------------------------------------
// Concat Wq|Wk|Wv -> W3 [1024, 3072], bq|bk|bv -> b3 [3072]
// ---------------------------------------------------------------------------
__global__ __launch_bounds__(256) void concat3(
    const float* __restrict__ Wq, const float* __restrict__ Wk,
    const float* __restrict__ Wv, const float* __restrict__ bq,
    const float* __restrict__ bk, const float* __restrict__ bv,
    float* __restrict__ W3, float* __restrict__ b3)
{
    const int idx = blockIdx.x * 256 + threadIdx.x;
    const int k = idx / QKV_N, n = idx % QKV_N;
    const int sel = n >> 10, col = n & 1023;
    const float* W = sel == 0 ? Wq : (sel == 1 ? Wk : Wv);
    W3[idx] = W[k * D_MODEL + col];
    if (idx < QKV_N) {
        const float* b = sel == 0 ? bq : (sel == 1 ? bk : bv);
        b3[idx] = b[col];
    }
}

// ---------------------------------------------------------------------------
// V [S,1024] fp32 -> Vt [1024,S] bf16 (transpose + convert)
// ---------------------------------------------------------------------------
__global__ __launch_bounds__(256) void vtrans(
    const float* __restrict__ V, __nv_bfloat16* __restrict__ Vt)
{
    __shared__ float t[64][33];
    const int k0 = blockIdx.x * 64;
    const int d0 = blockIdx.y * 32;
    const int x = threadIdx.x & 31;
    const int y = threadIdx.x >> 5;
#pragma unroll
    for (int i = 0; i < 64; i += 8)
        t[y + i][x] = V[(size_t)(k0 + y + i) * D_MODEL + d0 + x];
    __syncthreads();
    uint32_t* Vt32 = (uint32_t*)Vt;
#pragma unroll
    for (int p = 0; p < 4; p++) {
        const int d = y + 8 * p;
        const int j = x;
        uint32_t v = pack_bf16(t[2 * j][d], t[2 * j + 1][d]);
        Vt32[(size_t)(d0 + d) * (S_LEN / 2) + (k0 >> 1) + j] = v;
    }
}

// ---------------------------------------------------------------------------
// LayerNorm (unbiased var ddof=1, denom = sqrt(var)+eps)
// ---------------------------------------------------------------------------
__global__ __launch_bounds__(256) void ln_kernel(
    const float* __restrict__ x, const float* __restrict__ alpha,
    const float* __restrict__ beta, float* __restrict__ y)
{
    const int row = blockIdx.x;
    const float4* xr = (const float4*)(x + (size_t)row * D_MODEL);
    float4* yr = (float4*)(y + (size_t)row * D_MODEL);
    const int tid = threadIdx.x;

    float4 xl = xr[tid];
    float s = xl.x + xl.y + xl.z + xl.w;

    __shared__ float sh[8];
#pragma unroll
    for (int o = 16; o > 0; o >>= 1) s += __shfl_xor_sync(0xffffffffu, s, o);
    if ((tid & 31) == 0) sh[tid >> 5] = s;
    __syncthreads();
    float mu = 0.f;
#pragma unroll
    for (int i = 0; i < 8; i++) mu += sh[i];
    mu *= (1.0f / D_MODEL);
    __syncthreads();

    float dx = xl.x - mu, dy = xl.y - mu, dz = xl.z - mu, dw = xl.w - mu;
    float v = dx * dx + dy * dy + dz * dz + dw * dw;
#pragma unroll
    for (int o = 16; o > 0; o >>= 1) v += __shfl_xor_sync(0xffffffffu, v, o);
    if ((tid & 31) == 0) sh[tid >> 5] = v;
    __syncthreads();
    float var = 0.f;
#pragma unroll
    for (int i = 0; i < 8; i++) var += sh[i];
    var *= (1.0f / (D_MODEL - 1));

    const float a = alpha[0], b = beta[0];
    const float inv = a / (sqrtf(var) + 1e-6f);
    float4 o;
    o.x = dx * inv + b; o.y = dy * inv + b;
    o.z = dz * inv + b; o.w = dw * inv + b;
    yr[tid] = o;
}

// ---------------------------------------------------------------------------
// TF32 GEMM: C = A[M,K] @ W[K,N] + bias (+relu) (+residual)
// BM=128 BN=256 BK=32, 256 threads (8 warps, 64x64 warp tiles), 1 CTA/SM,
// 3-stage cp.async, 1 barrier/k-tile, ldmatrix a-frags, double-buffered
// fragments. QKV mode (C1 != nullptr): Q,K outputs bf16; V output fp32.
// ---------------------------------------------------------------------------
#define ASTR 36
#define BSTR 264                     // 256 + 8 pad; 264 % 32 == 8 -> LDS CF
#define A_TILE (128 * ASTR)          // 4608 floats
#define B_TILE (32 * BSTR)           // 8448 floats
#define STG_F  (A_TILE + B_TILE)     // 13056 floats
#define MM_SMEM (3 * STG_F * 4)      // 156672 B

template<bool RELU, bool RES>
__global__ __launch_bounds__(256, 1) void mm_tf32(
    const float* __restrict__ A, const float* __restrict__ W,
    const float* __restrict__ bias, const float* __restrict__ Rsd,
    float* __restrict__ C0, float* __restrict__ C1, float* __restrict__ C2,
    int M, int N, int K)
{
    extern __shared__ float smg[];

    const int tid  = threadIdx.x;
    const int warp = tid >> 5, lane = tid & 31;
    const int r = lane >> 2, c = lane & 3;
    const int wm = (warp >> 2) * 64, wn = (warp & 3) * 64;
    const int m0 = blockIdx.y * 128, n0 = blockIdx.x * 256;

    const uint32_t s0 = smem_u32(smg);

    // ldmatrix lane addressing for A
    const int g2 = lane >> 3, rowin = lane & 7;
    const uint32_t aLane = (uint32_t)((((g2 & 1) * 8 + rowin) * ASTR + (g2 >> 1) * 4) * 4);

    float acc[4][8][4];
#pragma unroll
    for (int i = 0; i < 4; i++)
#pragma unroll
        for (int j = 0; j < 8; j++)
#pragma unroll
            for (int k = 0; k < 4; k++) acc[i][j][k] = 0.f;

    const int NK = K >> 5;

    auto load_tile = [&](int kt, int st) {
        const uint32_t ab = s0 + (uint32_t)(st * STG_F) * 4u;
        const uint32_t bb = ab + (uint32_t)A_TILE * 4u;
#pragma unroll
        for (int i = 0; i < 4; i++) {             // A: 1024 chunks
            const int id = tid + 256 * i;
            const int ar = id >> 3, akc = id & 7;
            CP_ASYNC16(ab + (uint32_t)(ar * ASTR + akc * 4) * 4u,
                       A + (size_t)(m0 + ar) * K + kt * 32 + akc * 4);
        }
#pragma unroll
        for (int i = 0; i < 8; i++) {             // B: 2048 chunks
            const int id = tid + 256 * i;
            const int br = id >> 6, bnc = id & 63;
            CP_ASYNC16(bb + (uint32_t)(br * BSTR + bnc * 4) * 4u,
                       W + (size_t)(kt * 32 + br) * N + n0 + bnc * 4);
        }
    };

    load_tile(0, 0);
    CP_COMMIT();
    load_tile(1, 1);
    CP_COMMIT();

    for (int kt = 0; kt < NK; kt++) {
        const int st = kt - (kt / 3) * 3;
        CP_WAIT(1);
        __syncthreads();
        if (kt + 2 < NK) {
            const int s2 = (kt + 2) - ((kt + 2) / 3) * 3;
            load_tile(kt + 2, s2);
        }
        CP_COMMIT();

        const uint32_t aWarp = s0 + (uint32_t)(st * STG_F + wm * ASTR) * 4u + aLane;
        const float* Bb = smg + st * STG_F + A_TILE;

        // double-buffered fragments
        uint32_t a[2][4][4], b[2][8][2];
#pragma unroll
        for (int fm = 0; fm < 4; fm++)
            ldsm_x4(a[0][fm], aWarp + (uint32_t)((fm * 16 * ASTR) * 4));
#pragma unroll
        for (int fn = 0; fn < 8; fn++) {
            const float* q = Bb + c * BSTR + wn + fn * 8 + r;
            b[0][fn][0] = f2u(q[0]);
            b[0][fn][1] = f2u(q[4 * BSTR]);
        }

#pragma unroll
        for (int ks = 0; ks < 4; ks++) {
            const int cur = ks & 1;
            if (ks < 3) {
                const int nxt = cur ^ 1;
#pragma unroll
                for (int fm = 0; fm < 4; fm++)
                    ldsm_x4(a[nxt][fm],
                            aWarp + (uint32_t)((fm * 16 * ASTR + (ks + 1) * 8) * 4));
#pragma unroll
                for (int fn = 0; fn < 8; fn++) {
                    const float* q = Bb + ((ks + 1) * 8 + c) * BSTR + wn + fn * 8 + r;
                    b[nxt][fn][0] = f2u(q[0]);
                    b[nxt][fn][1] = f2u(q[4 * BSTR]);
                }
            }
#pragma unroll
            for (int fm = 0; fm < 4; fm++)
#pragma unroll
                for (int fn = 0; fn < 8; fn++)
                    mma_tf32(acc[fm][fn], a[cur][fm], b[cur][fn][0], b[cur][fn][1]);
        }
    }

    if (C1 != nullptr) {
        const int sel = n0 >> 10;
        const int nl0 = n0 & 1023;
        if (sel < 2) {
            __nv_bfloat16* Cb = (__nv_bfloat16*)(sel == 0 ? (void*)C0 : (void*)C1);
#pragma unroll
            for (int fm = 0; fm < 4; fm++) {
                const int row0 = m0 + wm + fm * 16 + r;
                const int row1 = row0 + 8;
#pragma unroll
                for (int fn = 0; fn < 8; fn++) {
                    const int colg = n0 + wn + fn * 8 + 2 * c;
                    const int col  = nl0 + wn + fn * 8 + 2 * c;
                    float2 bi = *(const float2*)&bias[colg];
                    uint32_t p0 = pack_bf16(acc[fm][fn][0] + bi.x, acc[fm][fn][1] + bi.y);
                    uint32_t p1 = pack_bf16(acc[fm][fn][2] + bi.x, acc[fm][fn][3] + bi.y);
                    *(uint32_t*)&Cb[(size_t)row0 * 1024 + col] = p0;
                    *(uint32_t*)&Cb[(size_t)row1 * 1024 + col] = p1;
                }
            }
        } else {
#pragma unroll
            for (int fm = 0; fm < 4; fm++) {
                const int row0 = m0 + wm + fm * 16 + r;
                const int row1 = row0 + 8;
#pragma unroll
                for (int fn = 0; fn < 8; fn++) {
                    const int colg = n0 + wn + fn * 8 + 2 * c;
                    const int col  = nl0 + wn + fn * 8 + 2 * c;
                    float2 bi = *(const float2*)&bias[colg];
                    *(float2*)&C2[(size_t)row0 * 1024 + col] =
                        make_float2(acc[fm][fn][0] + bi.x, acc[fm][fn][1] + bi.y);
                    *(float2*)&C2[(size_t)row1 * 1024 + col] =
                        make_float2(acc[fm][fn][2] + bi.x, acc[fm][fn][3] + bi.y);
                }
            }
        }
        return;
    }

#pragma unroll
    for (int fm = 0; fm < 4; fm++) {
        const int row0 = m0 + wm + fm * 16 + r;
        const int row1 = row0 + 8;
#pragma unroll
        for (int fn = 0; fn < 8; fn++) {
            const int col = n0 + wn + fn * 8 + 2 * c;
            float2 bi = *(const float2*)&bias[col];
            float v0 = acc[fm][fn][0] + bi.x;
            float v1 = acc[fm][fn][1] + bi.y;
            float v2 = acc[fm][fn][2] + bi.x;
            float v3 = acc[fm][fn][3] + bi.y;
            if (RELU) {
                v0 = fmaxf(v0, 0.f); v1 = fmaxf(v1, 0.f);
                v2 = fmaxf(v2, 0.f); v3 = fmaxf(v3, 0.f);
            }
            if (RES) {
                float2 r0 = *(const float2*)&Rsd[(size_t)row0 * N + col];
                float2 r1 = *(const float2*)&Rsd[(size_t)row1 * N + col];
                v0 += r0.x; v1 += r0.y; v2 += r1.x; v3 += r1.y;
            }
            *(float2*)&C0[(size_t)row0 * N + col] = make_float2(v0, v1);
            *(float2*)&C0[(size_t)row1 * N + col] = make_float2(v2, v3);
        }
    }
}

// ---------------------------------------------------------------------------
// Flash attention, bf16 m16n8k16. grid = (S/128, H), 128 threads, 2 CTAs/SM.
// (unchanged from R9)
// ---------------------------------------------------------------------------
#define ASTRU 36
#define QTILE_U (128 * ASTRU)
#define KTILE_U (64 * ASTRU)
#define ATT_SMEM ((QTILE_U + 4 * KTILE_U) * 4)
#define QK_SCALE 0.1803368801111364f       // 0.125 * log2(e)

__global__ __launch_bounds__(128, 2) void attn_bf16(
    const __nv_bfloat16* __restrict__ Qm, const __nv_bfloat16* __restrict__ Km,
    const __nv_bfloat16* __restrict__ Vt, float* __restrict__ Ctx)
{
    extern __shared__ uint32_t su[];
    uint32_t* Qs = su;                     // [128][36]
    uint32_t* Ks = Qs + QTILE_U;           // [2][64][36]
    uint32_t* Vs = Ks + 2 * KTILE_U;       // [2][64][36]

    const int tid  = threadIdx.x;
    const int warp = tid >> 5, lane = tid & 31;
    const int r = lane >> 2, c = lane & 3;
    const int wr = warp * 32;
    const int qb = blockIdx.x, h = blockIdx.y;
    const int cb = h * DK;

    const uint32_t qdst = smem_u32(Qs);
    const uint32_t kdst = smem_u32(Ks);
    const uint32_t vdst = smem_u32(Vs);

    const int g2 = lane >> 3, rowin = lane & 7;
    const uint32_t qLane = (uint32_t)(((g2 & 1) * 8 + rowin) * ASTRU + (g2 >> 1) * 4) * 4u;
    const uint32_t kLane = (uint32_t)(rowin * ASTRU + (g2 & 1) * 4) * 4u;

#pragma unroll
    for (int i = 0; i < 8; i++) {
        int id = tid + 128 * i;
        int row = id >> 3, ch = id & 7;
        CP_ASYNC16(qdst + (uint32_t)(row * ASTRU + ch * 4) * 4u,
                   Qm + (size_t)(qb * 128 + row) * D_MODEL + cb + ch * 8);
    }
#pragma unroll
    for (int i = 0; i < 4; i++) {
        int id = tid + 128 * i;
        int row = id >> 3, ch = id & 7;
        CP_ASYNC16(kdst + (uint32_t)(row * ASTRU + ch * 4) * 4u,
                   Km + (size_t)row * D_MODEL + cb + ch * 8);
        CP_ASYNC16(vdst + (uint32_t)(row * ASTRU + ch * 4) * 4u,
                   Vt + (size_t)(cb + row) * S_LEN + ch * 8);
    }
    CP_COMMIT();
    CP_WAIT(0);
    __syncthreads();

    const uint32_t qWarp = qdst + (uint32_t)(wr * ASTRU) * 4u + qLane;

    float mrow[2][2] = {{-1e30f, -1e30f}, {-1e30f, -1e30f}};
    float lrow[2][2] = {{0.f, 0.f}, {0.f, 0.f}};
    float acc[2][8][4];
#pragma unroll
    for (int i = 0; i < 2; i++)
#pragma unroll
        for (int j = 0; j < 8; j++)
#pragma unroll
            for (int k = 0; k < 4; k++) acc[i][j][k] = 0.f;

    for (int kt = 0; kt < S_LEN / 64; kt++) {
        const int buf = kt & 1;

        if (kt > 0) {
            CP_WAIT(0);
            __syncthreads();
        }
        if (kt + 1 < S_LEN / 64) {
            const int nb = buf ^ 1;
#pragma unroll
            for (int i = 0; i < 4; i++) {
                int id = tid + 128 * i;
                int row = id >> 3, ch = id & 7;
                CP_ASYNC16(kdst + (uint32_t)(nb * KTILE_U + row * ASTRU + ch * 4) * 4u,
                           Km + (size_t)((kt + 1) * 64 + row) * D_MODEL + cb + ch * 8);
                CP_ASYNC16(vdst + (uint32_t)(nb * KTILE_U + row * ASTRU + ch * 4) * 4u,
                           Vt + (size_t)(cb + row) * S_LEN + (kt + 1) * 64 + ch * 8);
            }
            CP_COMMIT();
        }

        float s[2][8][4];
#pragma unroll
        for (int i = 0; i < 2; i++)
#pragma unroll
            for (int j = 0; j < 8; j++)
#pragma unroll
                for (int k = 0; k < 4; k++) s[i][j][k] = 0.f;

        const uint32_t kTile = kdst + (uint32_t)(buf * KTILE_U) * 4u + kLane;
#pragma unroll
        for (int ks = 0; ks < 4; ks++) {
            uint32_t qf0[4], qf1[4];
            ldsm_x4(qf0, qWarp + (uint32_t)((ks * 8) * 4));
            ldsm_x4(qf1, qWarp + (uint32_t)((16 * ASTRU + ks * 8) * 4));
#pragma unroll
            for (int fn = 0; fn < 8; fn++) {
                uint32_t b0, b1;
                ldsm_x2(b0, b1, kTile + (uint32_t)((8 * fn * ASTRU + ks * 8) * 4));
                mma_bf16(s[0][fn], qf0, b0, b1);
                mma_bf16(s[1][fn], qf1, b0, b1);
            }
        }

        uint32_t pa[2][4][4];
#pragma unroll
        for (int fm = 0; fm < 2; fm++) {
            float mx0 = -1e30f, mx1 = -1e30f;
#pragma unroll
            for (int fn = 0; fn < 8; fn++) {
                mx0 = fmaxf(mx0, fmaxf(s[fm][fn][0], s[fm][fn][1]));
                mx1 = fmaxf(mx1, fmaxf(s[fm][fn][2], s[fm][fn][3]));
            }
            mx0 = fmaxf(mx0, __shfl_xor_sync(0xffffffffu, mx0, 1));
            mx0 = fmaxf(mx0, __shfl_xor_sync(0xffffffffu, mx0, 2));
            mx1 = fmaxf(mx1, __shfl_xor_sync(0xffffffffu, mx1, 1));
            mx1 = fmaxf(mx1, __shfl_xor_sync(0xffffffffu, mx1, 2));

            const float mn0 = fmaxf(mrow[fm][0], mx0);
            const float mn1 = fmaxf(mrow[fm][1], mx1);
            const float emn0 = mn0 * QK_SCALE;
            const float emn1 = mn1 * QK_SCALE;
            const float sc0 = ex2(fmaf(mrow[fm][0], QK_SCALE, -emn0));
            const float sc1 = ex2(fmaf(mrow[fm][1], QK_SCALE, -emn1));
            float ls0 = 0.f, ls1 = 0.f;
#pragma unroll
            for (int fn = 0; fn < 8; fn++) {
                float e0 = ex2(fmaf(s[fm][fn][0], QK_SCALE, -emn0));
                float e1 = ex2(fmaf(s[fm][fn][1], QK_SCALE, -emn0));
                float e2 = ex2(fmaf(s[fm][fn][2], QK_SCALE, -emn1));
                float e3 = ex2(fmaf(s[fm][fn][3], QK_SCALE, -emn1));
                ls0 += e0 + e1;
                ls1 += e2 + e3;
                pa[fm][fn >> 1][(fn & 1) * 2 + 0] = pack_bf16(e0, e1);
                pa[fm][fn >> 1][(fn & 1) * 2 + 1] = pack_bf16(e2, e3);
            }
            ls0 += __shfl_xor_sync(0xffffffffu, ls0, 1);
            ls0 += __shfl_xor_sync(0xffffffffu, ls0, 2);
            ls1 += __shfl_xor_sync(0xffffffffu, ls1, 1);
            ls1 += __shfl_xor_sync(0xffffffffu, ls1, 2);

            lrow[fm][0] = lrow[fm][0] * sc0 + ls0;
            lrow[fm][1] = lrow[fm][1] * sc1 + ls1;
            mrow[fm][0] = mn0; mrow[fm][1] = mn1;

#pragma unroll
            for (int fn = 0; fn < 8; fn++) {
                acc[fm][fn][0] *= sc0; acc[fm][fn][1] *= sc0;
                acc[fm][fn][2] *= sc1; acc[fm][fn][3] *= sc1;
            }
        }

        const uint32_t vTile = vdst + (uint32_t)(buf * KTILE_U) * 4u + kLane;
#pragma unroll
        for (int ks = 0; ks < 4; ks++) {
#pragma unroll
            for (int fn = 0; fn < 8; fn++) {
                uint32_t b0, b1;
                ldsm_x2(b0, b1, vTile + (uint32_t)((8 * fn * ASTRU + ks * 8) * 4));
                mma_bf16(acc[0][fn], pa[0][ks], b0, b1);
                mma_bf16(acc[1][fn], pa[1][ks], b0, b1);
            }
        }
    }

#pragma unroll
    for (int fm = 0; fm < 2; fm++) {
        const float inv0 = 1.f / lrow[fm][0];
        const float inv1 = 1.f / lrow[fm][1];
        const int row0 = qb * 128 + wr + fm * 16 + r;
        const int row1 = row0 + 8;
#pragma unroll
        for (int fn = 0; fn < 8; fn++) {
            const int col = cb + fn * 8 + 2 * c;
            *(float2*)&Ctx[(size_t)row0 * D_MODEL + col] =
                make_float2(acc[fm][fn][0] * inv0, acc[fm][fn][1] * inv0);
            *(float2*)&Ctx[(size_t)row1 * D_MODEL + col] =
                make_float2(acc[fm][fn][2] * inv1, acc[fm][fn][3] * inv1);
        }
    }
}

// ---------------------------------------------------------------------------
extern "C" void kernel_launch(void* const* d_in, const int* in_sizes, int n_in,
                              void* d_out, int out_size)
{
    const float* x    = (const float*)d_in[0];
    const float* Wq   = (const float*)d_in[1];
    const float* bq   = (const float*)d_in[2];
    const float* Wk   = (const float*)d_in[3];
    const float* bk   = (const float*)d_in[4];
    const float* Wv   = (const float*)d_in[5];
    const float* bv   = (const float*)d_in[6];
    const float* Wo   = (const float*)d_in[7];
    const float* bo   = (const float*)d_in[8];
    const float* ln1a = (const float*)d_in[9];
    const float* ln1b = (const float*)d_in[10];
    const float* W1   = (const float*)d_in[11];
    const float* b1   = (const float*)d_in[12];
    const float* W2   = (const float*)d_in[13];
    const float* b2   = (const float*)d_in[14];
    const float* ln2a = (const float*)d_in[15];
    const float* ln2b = (const float*)d_in[16];
    float* out = (float*)d_out;

    float *h1, *Vm, *ctx, *x1, *h2, *f1, *W3, *b3;
    __nv_bfloat16 *Qb, *Kb, *Vt;
    cudaGetSymbolAddress((void**)&h1,  g_h1);
    cudaGetSymbolAddress((void**)&Qb,  g_Qb);
    cudaGetSymbolAddress((void**)&Kb,  g_Kb);
    cudaGetSymbolAddress((void**)&Vm,  g_V);
    cudaGetSymbolAddress((void**)&Vt,  g_Vt);
    cudaGetSymbolAddress((void**)&ctx, g_ctx);
    cudaGetSymbolAddress((void**)&x1,  g_x1);
    cudaGetSymbolAddress((void**)&h2,  g_h2);
    cudaGetSymbolAddress((void**)&f1,  g_f1);
    cudaGetSymbolAddress((void**)&W3,  g_W3);
    cudaGetSymbolAddress((void**)&b3,  g_b3);

    cudaFuncSetAttribute(mm_tf32<false, false>,
                         cudaFuncAttributeMaxDynamicSharedMemorySize, MM_SMEM);
    cudaFuncSetAttribute(mm_tf32<false, true>,
                         cudaFuncAttributeMaxDynamicSharedMemorySize, MM_SMEM);
    cudaFuncSetAttribute(mm_tf32<true, false>,
                         cudaFuncAttributeMaxDynamicSharedMemorySize, MM_SMEM);
    cudaFuncSetAttribute(attn_bf16,
                         cudaFuncAttributeMaxDynamicSharedMemorySize, ATT_SMEM);

    concat3<<<(D_MODEL * QKV_N) / 256, 256>>>(Wq, Wk, Wv, bq, bk, bv, W3, b3);

    const dim3 gQKV (QKV_N  / 256, S_LEN / 128);     // (12, 32)
    const dim3 gSmall(D_MODEL / 256, S_LEN / 128);   // (4, 32)
    const dim3 gFF1 (D_FF   / 256, S_LEN / 128);     // (16, 32)

    // residual 1
    ln_kernel<<<S_LEN, 256>>>(x, ln1a, ln1b, h1);
    mm_tf32<false, false><<<gQKV, 256, MM_SMEM>>>(h1, W3, b3, nullptr,
        (float*)Qb, (float*)Kb, Vm, S_LEN, QKV_N, D_MODEL);
    vtrans<<<dim3(S_LEN / 64, D_MODEL / 32), 256>>>(Vm, Vt);
    attn_bf16<<<dim3(S_LEN / 128, NUM_HEADS), 128, ATT_SMEM>>>(Qb, Kb, Vt, ctx);
    mm_tf32<false, true><<<gSmall, 256, MM_SMEM>>>(ctx, Wo, bo, x,
        x1, nullptr, nullptr, S_LEN, D_MODEL, D_MODEL);

    // residual 2
    ln_kernel<<<S_LEN, 256>>>(x1, ln2a, ln2b, h2);
    mm_tf32<true,  false><<<gFF1, 256, MM_SMEM>>>(h2, W1, b1, nullptr,
        f1, nullptr, nullptr, S_LEN, D_FF, D_MODEL);
    mm_tf32<false, true><<<gSmall, 256, MM_SMEM>>>(f1, W2, b2, x1,
        out, nullptr, nullptr, S_LEN, D_MODEL, D_FF);
}